// round 13
// baseline (speedup 1.0000x reference)
#include <cuda_runtime.h>
#include <cuda_fp16.h>
#include <math.h>
#include <stdint.h>

#define N_NODES 65536
#define N_EDGES 524288
#define HIDDEN 128
#define OUTDIM 10
#define NUM_GRAPHS 64
#define SLOT_CAP 64

// ---------------- scratch (device globals; no allocation allowed) ----------
__device__ __align__(16) static uint32_t g_h16[(size_t)N_NODES * 64];
__device__ __align__(16) static uint32_t g_ah[(size_t)N_NODES * 64];
__device__ static int      g_deg[N_NODES];
__device__ static int      g_slots[(size_t)N_NODES * SLOT_CAP];
__device__ static float    g_gsum[NUM_GRAPHS * HIDDEN];
__device__ static float    g_gcnt[NUM_GRAPHS];
__device__ static int      g_is64;
__device__ __align__(16) static uint32_t g_w16[3][HIDDEN * 64];

// ---------------- helpers ----------------------------------------------------
__device__ __forceinline__ int kperm(int w) {
    return (w & ~7) | (((w & 3) << 1) | ((w >> 2) & 1));
}

__device__ __forceinline__ float elu_fast(float v) {
    return v > 0.0f ? v : (__expf(v) - 1.0f);
}

__device__ __forceinline__ uint32_t pack_h2(float a, float b) {
    __half2 h = __floats2half2_rn(a, b);
    return *reinterpret_cast<uint32_t*>(&h);
}

__device__ __forceinline__ void mma_fp16(float* c, uint32_t a0, uint32_t a1,
                                         uint32_t a2, uint32_t a3,
                                         uint32_t b0, uint32_t b1) {
    asm volatile(
        "mma.sync.aligned.m16n8k16.row.col.f32.f16.f16.f32 "
        "{%0,%1,%2,%3}, {%4,%5,%6,%7}, {%8,%9}, {%0,%1,%2,%3};"
        : "+f"(c[0]), "+f"(c[1]), "+f"(c[2]), "+f"(c[3])
        : "r"(a0), "r"(a1), "r"(a2), "r"(a3), "r"(b0), "r"(b1));
}

// ---------------- index dtype detection (1 warp, parallel) -------------------
__global__ void detect_kernel(const unsigned int* __restrict__ w) {
    int lane = threadIdx.x;
    bool zero = true;
#pragma unroll
    for (int j = 0; j < 4; j++) {
        if (w[1 + 2 * (lane + 32 * j)] != 0u) zero = false;
    }
    unsigned int mask = __ballot_sync(0xffffffffu, zero);
    if (lane == 0) g_is64 = (mask == 0xffffffffu) ? 1 : 0;
}

__device__ __forceinline__ int load_idx(const void* p, int i, int is64) {
    if (is64) return (int)((const long long*)p)[i];
    return ((const int*)p)[i];
}

// ---------------- prep: zero scratch + W fp16 + features fp16 ----------------
__global__ void prep_kernel(const float* __restrict__ features,
                            const float* __restrict__ W1,
                            const float* __restrict__ W2,
                            const float* __restrict__ W3) {
    int i = blockIdx.x * blockDim.x + threadIdx.x;
    if (i < N_NODES) g_deg[i] = 0;
    if (i < NUM_GRAPHS * HIDDEN) g_gsum[i] = 0.0f;
    if (i < NUM_GRAPHS) g_gcnt[i] = 0.0f;
    if (i < 3 * HIDDEN * 64) {
        int layer = i / (HIDDEN * 64);
        int rem = i - layer * (HIDDEN * 64);
        int n = rem >> 6, w = rem & 63;
        const float* W = (layer == 0) ? W1 : (layer == 1) ? W2 : W3;
        float v0 = __ldg(W + (2 * w) * HIDDEN + n);
        float v1 = __ldg(W + (2 * w + 1) * HIDDEN + n);
        g_w16[layer][n * 64 + kperm(w)] = pack_h2(v0, v1);
    }
    if (i < (N_NODES * HIDDEN) / 4) {
        float4 f = __ldg((const float4*)features + i);
        uint2 u;
        u.x = pack_h2(f.x, f.y);
        u.y = pack_h2(f.z, f.w);
        *((uint2*)g_h16 + i) = u;
    }
}

// ---------------- bucketed inverse adjacency ---------------------------------
__global__ void build_kernel(const void* __restrict__ src,
                             const void* __restrict__ dst) {
    int e = blockIdx.x * blockDim.x + threadIdx.x;
    if (e >= N_EDGES) return;
    int is64 = g_is64;
    int d = load_idx(dst, e, is64);
    int s = load_idx(src, e, is64);
    int pos = atomicAdd(&g_deg[d], 1);
    if (pos < SLOT_CAP) g_slots[(size_t)d * SLOT_CAP + pos] = s;
}

// ---------------- gather-sum: 2 neighbors/iter, LDG.128 half-warps -----------
// Lanes 0-15 handle even neighbors, 16-31 odd; each lane loads 16B (uint4) so
// 16 lanes cover the full 256B fp16 row. Parity halves merged by shfl at end.
__global__ void gather_kernel(const uint32_t* __restrict__ h16,
                              uint32_t* __restrict__ ah) {
    int w = (blockIdx.x * blockDim.x + threadIdx.x) >> 5;
    int lane = threadIdx.x & 31;
    if (w >= N_NODES) return;
    int g = lane >> 4;          // parity this lane serves
    int sub = lane & 15;        // 16B chunk within row
    int deg = g_deg[w];
    if (deg > SLOT_CAP) deg = SLOT_CAP;
    const int* slots = g_slots + (size_t)w * SLOT_CAP;
    int s0 = (lane < deg) ? slots[lane] : 0;
    int s1 = (32 + lane < deg) ? slots[32 + lane] : 0;

    float acc[8];
#pragma unroll
    for (int k = 0; k < 8; k++) acc[k] = 0.0f;

    int cnt = (deg + 1) >> 1;
    for (int i = 0; i < cnt; i++) {
        int idx = 2 * i + g;
        int sa = __shfl_sync(0xffffffffu, s0, idx & 31);
        int sb = __shfl_sync(0xffffffffu, s1, idx & 31);
        int s = (idx < 32) ? sa : sb;
        if (idx < deg) {
            uint4 u = __ldg((const uint4*)(h16 + (size_t)s * 64) + sub);
            float2 f0 = __half22float2(*reinterpret_cast<__half2*>(&u.x));
            float2 f1 = __half22float2(*reinterpret_cast<__half2*>(&u.y));
            float2 f2 = __half22float2(*reinterpret_cast<__half2*>(&u.z));
            float2 f3 = __half22float2(*reinterpret_cast<__half2*>(&u.w));
            acc[0] += f0.x; acc[1] += f0.y; acc[2] += f1.x; acc[3] += f1.y;
            acc[4] += f2.x; acc[5] += f2.y; acc[6] += f3.x; acc[7] += f3.y;
        }
    }
    // merge parity halves: lane j (<16) += lane j+16
#pragma unroll
    for (int k = 0; k < 8; k++)
        acc[k] += __shfl_down_sync(0xffffffffu, acc[k], 16);

    if (g == 0) {
        size_t rowOff = (size_t)w * 64;
        int w0 = 4 * sub;
        ah[rowOff + kperm(w0)]     = pack_h2(acc[0], acc[1]);
        ah[rowOff + kperm(w0 + 1)] = pack_h2(acc[2], acc[3]);
        ah[rowOff + kperm(w0 + 2)] = pack_h2(acc[4], acc[5]);
        ah[rowOff + kperm(w0 + 3)] = pack_h2(acc[6], acc[7]);
    }
}

// ---------------- persistent single-pass fp16 mma GEMM ------------------------
#define AS_STR 68
#define SM_AH 0
#define SM_WH (64 * AS_STR)
#define GEMM_SMEM_WORDS ((64 + 128) * AS_STR)
#define GEMM_SMEM_BYTES (GEMM_SMEM_WORDS * 4)
#define GEMM_GRID 444
#define NUM_TILES (N_NODES / 64)

__global__ void __launch_bounds__(256, 3)
gemm_tc_kernel(const uint32_t* __restrict__ Ah,
               const uint32_t* __restrict__ Wp,
               const float* __restrict__ b, uint32_t* __restrict__ out16) {
    extern __shared__ __align__(16) uint32_t smem[];
    int tid = threadIdx.x;
    int lane = tid & 31, wid = tid >> 5;
    int gq = lane >> 2, tq = lane & 3;
    int warp_m = wid & 1, warp_n = wid >> 1;
    const int mBase = warp_m * 32;
    const int nBase = warp_n * 32;

    {
        const uint4* src = (const uint4*)Wp;
        for (int i = tid; i < 128 * 16; i += 256) {
            int n = i >> 4, c4 = i & 15;
            *(uint4*)(smem + SM_WH + n * AS_STR + c4 * 4) = __ldg(src + i);
        }
    }

    int tile = blockIdx.x;
    uint4 pa[4];
    if (tile < NUM_TILES) {
        const uint4* src = (const uint4*)(Ah + (size_t)tile * 64 * 64);
#pragma unroll
        for (int j = 0; j < 4; j++) pa[j] = __ldg(src + tid + 256 * j);
    }
    __syncthreads();

    while (tile < NUM_TILES) {
#pragma unroll
        for (int j = 0; j < 4; j++) {
            int i = tid + 256 * j;
            int r = i >> 4, c4 = i & 15;
            *(uint4*)(smem + SM_AH + r * AS_STR + c4 * 4) = pa[j];
        }
        __syncthreads();

        int next = tile + GEMM_GRID;
        if (next < NUM_TILES) {
            const uint4* src = (const uint4*)(Ah + (size_t)next * 64 * 64);
#pragma unroll
            for (int j = 0; j < 4; j++) pa[j] = __ldg(src + tid + 256 * j);
        }

        float acc[2][4][4];
#pragma unroll
        for (int mi = 0; mi < 2; mi++)
#pragma unroll
            for (int ni = 0; ni < 4; ni++)
#pragma unroll
                for (int r = 0; r < 4; r++) acc[mi][ni][r] = 0.0f;

#pragma unroll
        for (int ks = 0; ks < 8; ks++) {
            int kw = ks * 8 + 2 * tq;
            uint2 ah2[2][2];
#pragma unroll
            for (int mi = 0; mi < 2; mi++) {
                int r = mBase + mi * 16 + gq;
                ah2[mi][0] = *(const uint2*)(smem + SM_AH + r * AS_STR + kw);
                ah2[mi][1] = *(const uint2*)(smem + SM_AH + (r + 8) * AS_STR + kw);
            }
            uint2 bh[4];
#pragma unroll
            for (int ni = 0; ni < 4; ni++) {
                int c = nBase + ni * 8 + gq;
                bh[ni] = *(const uint2*)(smem + SM_WH + c * AS_STR + kw);
            }
#pragma unroll
            for (int mi = 0; mi < 2; mi++)
#pragma unroll
                for (int ni = 0; ni < 4; ni++)
                    mma_fp16(acc[mi][ni], ah2[mi][0].x, ah2[mi][1].x, ah2[mi][0].y, ah2[mi][1].y,
                             bh[ni].x, bh[ni].y);
        }

        size_t rowBase = (size_t)tile * 64;
#pragma unroll
        for (int mi = 0; mi < 2; mi++) {
            int r0 = mBase + mi * 16 + gq;
#pragma unroll
            for (int ni = 0; ni < 4; ni++) {
                int c0 = nBase + ni * 8 + 2 * tq;
                float2 bb = __ldg((const float2*)(b + c0));
                float v0 = elu_fast(acc[mi][ni][0] + bb.x);
                float v1 = elu_fast(acc[mi][ni][1] + bb.y);
                float v2 = elu_fast(acc[mi][ni][2] + bb.x);
                float v3 = elu_fast(acc[mi][ni][3] + bb.y);
                out16[(rowBase + r0) * 64 + (c0 >> 1)] = pack_h2(v0, v1);
                out16[(rowBase + r0 + 8) * 64 + (c0 >> 1)] = pack_h2(v2, v3);
            }
        }
        __syncthreads();
        tile = next;
    }
}

// ---------------- graph readout (fp16 h, sums + counts fused) -----------------
__global__ void readout_kernel(const uint32_t* __restrict__ h16,
                               const void* __restrict__ gid) {
    int t = threadIdx.x;
    int base = blockIdx.x * 128;
    int is64 = g_is64;
    const __half* hh = (const __half*)h16;
    int cur = load_idx(gid, base, is64);
    float acc = 0.0f;
    int runlen = 0;
    for (int n = 0; n < 128; n++) {
        int node = base + n;
        int g = load_idx(gid, node, is64);
        if (g != cur) {
            atomicAdd(&g_gsum[cur * HIDDEN + t], acc);
            if (t == 0) atomicAdd(&g_gcnt[cur], (float)runlen);
            acc = 0.0f; runlen = 0; cur = g;
        }
        acc += __half2float(hh[(size_t)node * HIDDEN + t]);
        runlen++;
    }
    atomicAdd(&g_gsum[cur * HIDDEN + t], acc);
    if (t == 0) atomicAdd(&g_gcnt[cur], (float)runlen);
}

__global__ void classifier_kernel(const float* __restrict__ Wc,
                                  const float* __restrict__ bc,
                                  float* __restrict__ out) {
    int t = blockIdx.x * blockDim.x + threadIdx.x;
    if (t >= NUM_GRAPHS * OUTDIM) return;
    int g = t / OUTDIM, o = t % OUTDIM;
    float c = fmaxf(g_gcnt[g], 1.0f);
    float inv = 1.0f / c;
    float acc = bc[o];
#pragma unroll 8
    for (int k = 0; k < HIDDEN; k++)
        acc += g_gsum[g * HIDDEN + k] * inv * Wc[k * OUTDIM + o];
    out[t] = acc;
}

// ---------------- launch -------------------------------------------------------
extern "C" void kernel_launch(void* const* d_in, const int* in_sizes, int n_in,
                              void* d_out, int out_size) {
    const float* features = (const float*)d_in[0];
    const void*  src      = d_in[1];
    const void*  dst      = d_in[2];
    const void*  gids     = d_in[3];
    const float* W1 = (const float*)d_in[4];
    const float* b1 = (const float*)d_in[5];
    const float* W2 = (const float*)d_in[6];
    const float* b2 = (const float*)d_in[7];
    const float* W3 = (const float*)d_in[8];
    const float* b3 = (const float*)d_in[9];
    const float* Wc = (const float*)d_in[10];
    const float* bc = (const float*)d_in[11];
    float* out = (float*)d_out;

    uint32_t* h16; cudaGetSymbolAddress((void**)&h16, g_h16);
    uint32_t* ah;  cudaGetSymbolAddress((void**)&ah, g_ah);
    uint32_t* w16; cudaGetSymbolAddress((void**)&w16, g_w16);

    cudaFuncSetAttribute(gemm_tc_kernel,
                         cudaFuncAttributeMaxDynamicSharedMemorySize, GEMM_SMEM_BYTES);

    detect_kernel<<<1, 32>>>((const unsigned int*)src);
    prep_kernel<<<(N_NODES * HIDDEN / 4) / 256, 256>>>(features, W1, W2, W3);
    build_kernel<<<N_EDGES / 256, 256>>>(src, dst);

    const int GATHER_BLOCKS = (N_NODES * 32) / 256;
    const int WSZ = HIDDEN * 64;

    gather_kernel<<<GATHER_BLOCKS, 256>>>(h16, ah);
    gemm_tc_kernel<<<GEMM_GRID, 256, GEMM_SMEM_BYTES>>>(ah, w16, b1, h16);
    gather_kernel<<<GATHER_BLOCKS, 256>>>(h16, ah);
    gemm_tc_kernel<<<GEMM_GRID, 256, GEMM_SMEM_BYTES>>>(ah, w16 + WSZ, b2, h16);
    gather_kernel<<<GATHER_BLOCKS, 256>>>(h16, ah);
    gemm_tc_kernel<<<GEMM_GRID, 256, GEMM_SMEM_BYTES>>>(ah, w16 + 2 * WSZ, b3, h16);

    readout_kernel<<<N_NODES / 128, 128>>>(h16, gids);
    classifier_kernel<<<1, NUM_GRAPHS * OUTDIM>>>(Wc, bc, out);
}

// round 14
// speedup vs baseline: 1.1496x; 1.1496x over previous
#include <cuda_runtime.h>
#include <cuda_fp16.h>
#include <math.h>
#include <stdint.h>

#define N_NODES 65536
#define N_EDGES 524288
#define HIDDEN 128
#define OUTDIM 10
#define NUM_GRAPHS 64
#define SLOT_CAP 64

// ---------------- scratch (device globals; no allocation allowed) ----------
__device__ __align__(16) static uint32_t g_h16[(size_t)N_NODES * 64];
__device__ __align__(16) static uint32_t g_ah[(size_t)N_NODES * 64];
__device__ static int      g_deg[N_NODES];
__device__ static int      g_slots[(size_t)N_NODES * SLOT_CAP];
__device__ static float    g_gsum[NUM_GRAPHS * HIDDEN];
__device__ static float    g_gcnt[NUM_GRAPHS];
__device__ static int      g_is64;
__device__ __align__(16) static uint32_t g_w16[3][HIDDEN * 64];

// ---------------- helpers ----------------------------------------------------
__device__ __forceinline__ int kperm(int w) {
    return (w & ~7) | (((w & 3) << 1) | ((w >> 2) & 1));
}

__device__ __forceinline__ float elu_fast(float v) {
    return v > 0.0f ? v : (__expf(v) - 1.0f);
}

__device__ __forceinline__ uint32_t pack_h2(float a, float b) {
    __half2 h = __floats2half2_rn(a, b);
    return *reinterpret_cast<uint32_t*>(&h);
}

__device__ __forceinline__ void mma_fp16(float* c, uint32_t a0, uint32_t a1,
                                         uint32_t a2, uint32_t a3,
                                         uint32_t b0, uint32_t b1) {
    asm volatile(
        "mma.sync.aligned.m16n8k16.row.col.f32.f16.f16.f32 "
        "{%0,%1,%2,%3}, {%4,%5,%6,%7}, {%8,%9}, {%0,%1,%2,%3};"
        : "+f"(c[0]), "+f"(c[1]), "+f"(c[2]), "+f"(c[3])
        : "r"(a0), "r"(a1), "r"(a2), "r"(a3), "r"(b0), "r"(b1));
}

// ---------------- index dtype detection (1 warp, parallel) -------------------
__global__ void detect_kernel(const unsigned int* __restrict__ w) {
    int lane = threadIdx.x;
    bool zero = true;
#pragma unroll
    for (int j = 0; j < 4; j++) {
        if (w[1 + 2 * (lane + 32 * j)] != 0u) zero = false;
    }
    unsigned int mask = __ballot_sync(0xffffffffu, zero);
    if (lane == 0) g_is64 = (mask == 0xffffffffu) ? 1 : 0;
}

__device__ __forceinline__ int load_idx(const void* p, int i, int is64) {
    if (is64) return (int)((const long long*)p)[i];
    return ((const int*)p)[i];
}

// ---------------- prep: zero scratch + W fp16 + features fp16 ----------------
__global__ void prep_kernel(const float* __restrict__ features,
                            const float* __restrict__ W1,
                            const float* __restrict__ W2,
                            const float* __restrict__ W3) {
    int i = blockIdx.x * blockDim.x + threadIdx.x;
    if (i < N_NODES) g_deg[i] = 0;
    if (i < NUM_GRAPHS * HIDDEN) g_gsum[i] = 0.0f;
    if (i < NUM_GRAPHS) g_gcnt[i] = 0.0f;
    if (i < 3 * HIDDEN * 64) {
        int layer = i / (HIDDEN * 64);
        int rem = i - layer * (HIDDEN * 64);
        int n = rem >> 6, w = rem & 63;
        const float* W = (layer == 0) ? W1 : (layer == 1) ? W2 : W3;
        float v0 = __ldg(W + (2 * w) * HIDDEN + n);
        float v1 = __ldg(W + (2 * w + 1) * HIDDEN + n);
        g_w16[layer][n * 64 + kperm(w)] = pack_h2(v0, v1);
    }
    if (i < (N_NODES * HIDDEN) / 4) {
        float4 f = __ldg((const float4*)features + i);
        uint2 u;
        u.x = pack_h2(f.x, f.y);
        u.y = pack_h2(f.z, f.w);
        *((uint2*)g_h16 + i) = u;
    }
}

// ---------------- bucketed inverse adjacency ---------------------------------
__global__ void build_kernel(const void* __restrict__ src,
                             const void* __restrict__ dst) {
    int e = blockIdx.x * blockDim.x + threadIdx.x;
    if (e >= N_EDGES) return;
    int is64 = g_is64;
    int d = load_idx(dst, e, is64);
    int s = load_idx(src, e, is64);
    int pos = atomicAdd(&g_deg[d], 1);
    if (pos < SLOT_CAP) g_slots[(size_t)d * SLOT_CAP + pos] = s;
}

// ---------------- gather-sum over fp16 rows -> fp16 A plane (permuted) -------
// R12-proven simple loop, split at 32 to remove the per-iter s0/s1 select.
__global__ void gather_kernel(const uint32_t* __restrict__ h16,
                              uint32_t* __restrict__ ah) {
    int w = (blockIdx.x * blockDim.x + threadIdx.x) >> 5;
    int lane = threadIdx.x & 31;
    if (w >= N_NODES) return;
    int deg = g_deg[w];
    if (deg > SLOT_CAP) deg = SLOT_CAP;
    const int* slots = g_slots + (size_t)w * SLOT_CAP;
    int s0 = (lane < deg) ? slots[lane] : 0;
    int s1 = (32 + lane < deg) ? slots[32 + lane] : 0;
    float4 acc = make_float4(0.f, 0.f, 0.f, 0.f);
    int d0 = (deg < 32) ? deg : 32;
    for (int i = 0; i < d0; i++) {
        int s = __shfl_sync(0xffffffffu, s0, i);
        uint2 u = __ldg((const uint2*)(h16 + (size_t)s * 64) + lane);
        float2 f01 = __half22float2(*reinterpret_cast<__half2*>(&u.x));
        float2 f23 = __half22float2(*reinterpret_cast<__half2*>(&u.y));
        acc.x += f01.x; acc.y += f01.y; acc.z += f23.x; acc.w += f23.y;
    }
    for (int i = 32; i < deg; i++) {
        int s = __shfl_sync(0xffffffffu, s1, i - 32);
        uint2 u = __ldg((const uint2*)(h16 + (size_t)s * 64) + lane);
        float2 f01 = __half22float2(*reinterpret_cast<__half2*>(&u.x));
        float2 f23 = __half22float2(*reinterpret_cast<__half2*>(&u.y));
        acc.x += f01.x; acc.y += f01.y; acc.z += f23.x; acc.w += f23.y;
    }
    size_t rowOff = (size_t)w * 64;
    ah[rowOff + kperm(2 * lane)]     = pack_h2(acc.x, acc.y);
    ah[rowOff + kperm(2 * lane + 1)] = pack_h2(acc.z, acc.w);
}

// ---------------- persistent single-pass fp16 mma GEMM ------------------------
#define AS_STR 68
#define SM_AH 0
#define SM_WH (64 * AS_STR)
#define GEMM_SMEM_WORDS ((64 + 128) * AS_STR)
#define GEMM_SMEM_BYTES (GEMM_SMEM_WORDS * 4)
#define GEMM_GRID 444
#define NUM_TILES (N_NODES / 64)

__global__ void __launch_bounds__(256, 3)
gemm_tc_kernel(const uint32_t* __restrict__ Ah,
               const uint32_t* __restrict__ Wp,
               const float* __restrict__ b, uint32_t* __restrict__ out16) {
    extern __shared__ __align__(16) uint32_t smem[];
    int tid = threadIdx.x;
    int lane = tid & 31, wid = tid >> 5;
    int gq = lane >> 2, tq = lane & 3;
    int warp_m = wid & 1, warp_n = wid >> 1;
    const int mBase = warp_m * 32;
    const int nBase = warp_n * 32;

    {
        const uint4* src = (const uint4*)Wp;
        for (int i = tid; i < 128 * 16; i += 256) {
            int n = i >> 4, c4 = i & 15;
            *(uint4*)(smem + SM_WH + n * AS_STR + c4 * 4) = __ldg(src + i);
        }
    }

    int tile = blockIdx.x;
    uint4 pa[4];
    if (tile < NUM_TILES) {
        const uint4* src = (const uint4*)(Ah + (size_t)tile * 64 * 64);
#pragma unroll
        for (int j = 0; j < 4; j++) pa[j] = __ldg(src + tid + 256 * j);
    }
    __syncthreads();

    while (tile < NUM_TILES) {
#pragma unroll
        for (int j = 0; j < 4; j++) {
            int i = tid + 256 * j;
            int r = i >> 4, c4 = i & 15;
            *(uint4*)(smem + SM_AH + r * AS_STR + c4 * 4) = pa[j];
        }
        __syncthreads();

        int next = tile + GEMM_GRID;
        if (next < NUM_TILES) {
            const uint4* src = (const uint4*)(Ah + (size_t)next * 64 * 64);
#pragma unroll
            for (int j = 0; j < 4; j++) pa[j] = __ldg(src + tid + 256 * j);
        }

        float acc[2][4][4];
#pragma unroll
        for (int mi = 0; mi < 2; mi++)
#pragma unroll
            for (int ni = 0; ni < 4; ni++)
#pragma unroll
                for (int r = 0; r < 4; r++) acc[mi][ni][r] = 0.0f;

#pragma unroll
        for (int ks = 0; ks < 8; ks++) {
            int kw = ks * 8 + 2 * tq;
            uint2 ah2[2][2];
#pragma unroll
            for (int mi = 0; mi < 2; mi++) {
                int r = mBase + mi * 16 + gq;
                ah2[mi][0] = *(const uint2*)(smem + SM_AH + r * AS_STR + kw);
                ah2[mi][1] = *(const uint2*)(smem + SM_AH + (r + 8) * AS_STR + kw);
            }
            uint2 bh[4];
#pragma unroll
            for (int ni = 0; ni < 4; ni++) {
                int c = nBase + ni * 8 + gq;
                bh[ni] = *(const uint2*)(smem + SM_WH + c * AS_STR + kw);
            }
#pragma unroll
            for (int mi = 0; mi < 2; mi++)
#pragma unroll
                for (int ni = 0; ni < 4; ni++)
                    mma_fp16(acc[mi][ni], ah2[mi][0].x, ah2[mi][1].x, ah2[mi][0].y, ah2[mi][1].y,
                             bh[ni].x, bh[ni].y);
        }

        size_t rowBase = (size_t)tile * 64;
#pragma unroll
        for (int mi = 0; mi < 2; mi++) {
            int r0 = mBase + mi * 16 + gq;
#pragma unroll
            for (int ni = 0; ni < 4; ni++) {
                int c0 = nBase + ni * 8 + 2 * tq;
                float2 bb = __ldg((const float2*)(b + c0));
                float v0 = elu_fast(acc[mi][ni][0] + bb.x);
                float v1 = elu_fast(acc[mi][ni][1] + bb.y);
                float v2 = elu_fast(acc[mi][ni][2] + bb.x);
                float v3 = elu_fast(acc[mi][ni][3] + bb.y);
                out16[(rowBase + r0) * 64 + (c0 >> 1)] = pack_h2(v0, v1);
                out16[(rowBase + r0 + 8) * 64 + (c0 >> 1)] = pack_h2(v2, v3);
            }
        }
        __syncthreads();
        tile = next;
    }
}

// ---------------- graph readout (64 nodes/block, sums + counts fused) ---------
__global__ void readout_kernel(const uint32_t* __restrict__ h16,
                               const void* __restrict__ gid) {
    int t = threadIdx.x;
    int base = blockIdx.x * 64;
    int is64 = g_is64;
    const __half* hh = (const __half*)h16;
    int cur = load_idx(gid, base, is64);
    float acc = 0.0f;
    int runlen = 0;
    for (int n = 0; n < 64; n++) {
        int node = base + n;
        int g = load_idx(gid, node, is64);
        if (g != cur) {
            atomicAdd(&g_gsum[cur * HIDDEN + t], acc);
            if (t == 0) atomicAdd(&g_gcnt[cur], (float)runlen);
            acc = 0.0f; runlen = 0; cur = g;
        }
        acc += __half2float(hh[(size_t)node * HIDDEN + t]);
        runlen++;
    }
    atomicAdd(&g_gsum[cur * HIDDEN + t], acc);
    if (t == 0) atomicAdd(&g_gcnt[cur], (float)runlen);
}

__global__ void classifier_kernel(const float* __restrict__ Wc,
                                  const float* __restrict__ bc,
                                  float* __restrict__ out) {
    int t = blockIdx.x * blockDim.x + threadIdx.x;
    if (t >= NUM_GRAPHS * OUTDIM) return;
    int g = t / OUTDIM, o = t % OUTDIM;
    float c = fmaxf(g_gcnt[g], 1.0f);
    float inv = 1.0f / c;
    float acc = bc[o];
#pragma unroll 8
    for (int k = 0; k < HIDDEN; k++)
        acc += g_gsum[g * HIDDEN + k] * inv * Wc[k * OUTDIM + o];
    out[t] = acc;
}

// ---------------- launch -------------------------------------------------------
extern "C" void kernel_launch(void* const* d_in, const int* in_sizes, int n_in,
                              void* d_out, int out_size) {
    const float* features = (const float*)d_in[0];
    const void*  src      = d_in[1];
    const void*  dst      = d_in[2];
    const void*  gids     = d_in[3];
    const float* W1 = (const float*)d_in[4];
    const float* b1 = (const float*)d_in[5];
    const float* W2 = (const float*)d_in[6];
    const float* b2 = (const float*)d_in[7];
    const float* W3 = (const float*)d_in[8];
    const float* b3 = (const float*)d_in[9];
    const float* Wc = (const float*)d_in[10];
    const float* bc = (const float*)d_in[11];
    float* out = (float*)d_out;

    uint32_t* h16; cudaGetSymbolAddress((void**)&h16, g_h16);
    uint32_t* ah;  cudaGetSymbolAddress((void**)&ah, g_ah);
    uint32_t* w16; cudaGetSymbolAddress((void**)&w16, g_w16);

    cudaFuncSetAttribute(gemm_tc_kernel,
                         cudaFuncAttributeMaxDynamicSharedMemorySize, GEMM_SMEM_BYTES);

    detect_kernel<<<1, 32>>>((const unsigned int*)src);
    prep_kernel<<<(N_NODES * HIDDEN / 4) / 256, 256>>>(features, W1, W2, W3);
    build_kernel<<<N_EDGES / 256, 256>>>(src, dst);

    const int GATHER_BLOCKS = (N_NODES * 32) / 256;
    const int WSZ = HIDDEN * 64;

    gather_kernel<<<GATHER_BLOCKS, 256>>>(h16, ah);
    gemm_tc_kernel<<<GEMM_GRID, 256, GEMM_SMEM_BYTES>>>(ah, w16, b1, h16);
    gather_kernel<<<GATHER_BLOCKS, 256>>>(h16, ah);
    gemm_tc_kernel<<<GEMM_GRID, 256, GEMM_SMEM_BYTES>>>(ah, w16 + WSZ, b2, h16);
    gather_kernel<<<GATHER_BLOCKS, 256>>>(h16, ah);
    gemm_tc_kernel<<<GEMM_GRID, 256, GEMM_SMEM_BYTES>>>(ah, w16 + 2 * WSZ, b3, h16);

    readout_kernel<<<N_NODES / 64, 128>>>(h16, gids);
    classifier_kernel<<<1, NUM_GRAPHS * OUTDIM>>>(Wc, bc, out);
}

// round 15
// speedup vs baseline: 1.1543x; 1.0041x over previous
#include <cuda_runtime.h>
#include <cuda_fp16.h>
#include <math.h>
#include <stdint.h>

#define N_NODES 65536
#define N_EDGES 524288
#define HIDDEN 128
#define OUTDIM 10
#define NUM_GRAPHS 64
#define SLOT_CAP 64

// ---------------- scratch (device globals; no allocation allowed) ----------
__device__ __align__(16) static uint32_t g_h16[(size_t)N_NODES * 64];
__device__ __align__(16) static uint32_t g_ah[(size_t)N_NODES * 64];
__device__ static int      g_deg[N_NODES];
__device__ static int      g_slots[(size_t)N_NODES * SLOT_CAP];
__device__ static float    g_gsum[NUM_GRAPHS * HIDDEN];
__device__ static float    g_gcnt[NUM_GRAPHS];
__device__ static int      g_is64;
__device__ __align__(16) static uint32_t g_w16[3][HIDDEN * 64];

// ---------------- helpers ----------------------------------------------------
__device__ __forceinline__ int kperm(int w) {
    return (w & ~7) | (((w & 3) << 1) | ((w >> 2) & 1));
}

__device__ __forceinline__ float elu_fast(float v) {
    return v > 0.0f ? v : (__expf(v) - 1.0f);
}

__device__ __forceinline__ uint32_t pack_h2(float a, float b) {
    __half2 h = __floats2half2_rn(a, b);
    return *reinterpret_cast<uint32_t*>(&h);
}

__device__ __forceinline__ void mma_fp16(float* c, uint32_t a0, uint32_t a1,
                                         uint32_t a2, uint32_t a3,
                                         uint32_t b0, uint32_t b1) {
    asm volatile(
        "mma.sync.aligned.m16n8k16.row.col.f32.f16.f16.f32 "
        "{%0,%1,%2,%3}, {%4,%5,%6,%7}, {%8,%9}, {%0,%1,%2,%3};"
        : "+f"(c[0]), "+f"(c[1]), "+f"(c[2]), "+f"(c[3])
        : "r"(a0), "r"(a1), "r"(a2), "r"(a3), "r"(b0), "r"(b1));
}

// ---------------- index dtype detection (1 warp, parallel) -------------------
__global__ void detect_kernel(const unsigned int* __restrict__ w) {
    int lane = threadIdx.x;
    bool zero = true;
#pragma unroll
    for (int j = 0; j < 4; j++) {
        if (w[1 + 2 * (lane + 32 * j)] != 0u) zero = false;
    }
    unsigned int mask = __ballot_sync(0xffffffffu, zero);
    if (lane == 0) g_is64 = (mask == 0xffffffffu) ? 1 : 0;
}

__device__ __forceinline__ int load_idx(const void* p, int i, int is64) {
    if (is64) return (int)((const long long*)p)[i];
    return ((const int*)p)[i];
}

// ---------------- prep+build: W fp16, features fp16, adjacency, zeroing ------
// g_deg is zeroed by cudaMemsetAsync BEFORE this kernel (build atomics race
// with in-kernel zeroing otherwise). gsum/gcnt zeroing is safe here (readout
// runs much later).
__global__ void prep_build_kernel(const float* __restrict__ features,
                                  const float* __restrict__ W1,
                                  const float* __restrict__ W2,
                                  const float* __restrict__ W3,
                                  const void* __restrict__ src,
                                  const void* __restrict__ dst) {
    int i = blockIdx.x * blockDim.x + threadIdx.x;
    if (i < NUM_GRAPHS * HIDDEN) g_gsum[i] = 0.0f;
    if (i < NUM_GRAPHS) g_gcnt[i] = 0.0f;
    if (i < 3 * HIDDEN * 64) {
        int layer = i / (HIDDEN * 64);
        int rem = i - layer * (HIDDEN * 64);
        int n = rem >> 6, w = rem & 63;
        const float* W = (layer == 0) ? W1 : (layer == 1) ? W2 : W3;
        float v0 = __ldg(W + (2 * w) * HIDDEN + n);
        float v1 = __ldg(W + (2 * w + 1) * HIDDEN + n);
        g_w16[layer][n * 64 + kperm(w)] = pack_h2(v0, v1);
    }
    if (i < N_EDGES) {
        int is64 = g_is64;
        int d = load_idx(dst, i, is64);
        int s = load_idx(src, i, is64);
        int pos = atomicAdd(&g_deg[d], 1);
        if (pos < SLOT_CAP) g_slots[(size_t)d * SLOT_CAP + pos] = s;
    }
    if (i < (N_NODES * HIDDEN) / 4) {
        float4 f = __ldg((const float4*)features + i);
        uint2 u;
        u.x = pack_h2(f.x, f.y);
        u.y = pack_h2(f.z, f.w);
        *((uint2*)g_h16 + i) = u;
    }
}

// ---------------- gather-sum over fp16 rows -> fp16 A plane (permuted) -------
// R14-proven: simple loop split at 32 (no per-iter s0/s1 select).
__global__ void gather_kernel(const uint32_t* __restrict__ h16,
                              uint32_t* __restrict__ ah) {
    int w = (blockIdx.x * blockDim.x + threadIdx.x) >> 5;
    int lane = threadIdx.x & 31;
    if (w >= N_NODES) return;
    int deg = g_deg[w];
    if (deg > SLOT_CAP) deg = SLOT_CAP;
    const int* slots = g_slots + (size_t)w * SLOT_CAP;
    int s0 = (lane < deg) ? slots[lane] : 0;
    int s1 = (32 + lane < deg) ? slots[32 + lane] : 0;
    float4 acc = make_float4(0.f, 0.f, 0.f, 0.f);
    int d0 = (deg < 32) ? deg : 32;
    for (int i = 0; i < d0; i++) {
        int s = __shfl_sync(0xffffffffu, s0, i);
        uint2 u = __ldg((const uint2*)(h16 + (size_t)s * 64) + lane);
        float2 f01 = __half22float2(*reinterpret_cast<__half2*>(&u.x));
        float2 f23 = __half22float2(*reinterpret_cast<__half2*>(&u.y));
        acc.x += f01.x; acc.y += f01.y; acc.z += f23.x; acc.w += f23.y;
    }
    for (int i = 32; i < deg; i++) {
        int s = __shfl_sync(0xffffffffu, s1, i - 32);
        uint2 u = __ldg((const uint2*)(h16 + (size_t)s * 64) + lane);
        float2 f01 = __half22float2(*reinterpret_cast<__half2*>(&u.x));
        float2 f23 = __half22float2(*reinterpret_cast<__half2*>(&u.y));
        acc.x += f01.x; acc.y += f01.y; acc.z += f23.x; acc.w += f23.y;
    }
    size_t rowOff = (size_t)w * 64;
    ah[rowOff + kperm(2 * lane)]     = pack_h2(acc.x, acc.y);
    ah[rowOff + kperm(2 * lane + 1)] = pack_h2(acc.z, acc.w);
}

// ---------------- persistent single-pass fp16 mma GEMM ------------------------
#define AS_STR 68
#define SM_AH 0
#define SM_WH (64 * AS_STR)
#define GEMM_SMEM_WORDS ((64 + 128) * AS_STR)
#define GEMM_SMEM_BYTES (GEMM_SMEM_WORDS * 4)
#define GEMM_GRID 444
#define NUM_TILES (N_NODES / 64)

__global__ void __launch_bounds__(256, 3)
gemm_tc_kernel(const uint32_t* __restrict__ Ah,
               const uint32_t* __restrict__ Wp,
               const float* __restrict__ b, uint32_t* __restrict__ out16) {
    extern __shared__ __align__(16) uint32_t smem[];
    int tid = threadIdx.x;
    int lane = tid & 31, wid = tid >> 5;
    int gq = lane >> 2, tq = lane & 3;
    int warp_m = wid & 1, warp_n = wid >> 1;
    const int mBase = warp_m * 32;
    const int nBase = warp_n * 32;

    {
        const uint4* src = (const uint4*)Wp;
        for (int i = tid; i < 128 * 16; i += 256) {
            int n = i >> 4, c4 = i & 15;
            *(uint4*)(smem + SM_WH + n * AS_STR + c4 * 4) = __ldg(src + i);
        }
    }

    int tile = blockIdx.x;
    uint4 pa[4];
    if (tile < NUM_TILES) {
        const uint4* src = (const uint4*)(Ah + (size_t)tile * 64 * 64);
#pragma unroll
        for (int j = 0; j < 4; j++) pa[j] = __ldg(src + tid + 256 * j);
    }
    __syncthreads();

    while (tile < NUM_TILES) {
#pragma unroll
        for (int j = 0; j < 4; j++) {
            int i = tid + 256 * j;
            int r = i >> 4, c4 = i & 15;
            *(uint4*)(smem + SM_AH + r * AS_STR + c4 * 4) = pa[j];
        }
        __syncthreads();

        int next = tile + GEMM_GRID;
        if (next < NUM_TILES) {
            const uint4* src = (const uint4*)(Ah + (size_t)next * 64 * 64);
#pragma unroll
            for (int j = 0; j < 4; j++) pa[j] = __ldg(src + tid + 256 * j);
        }

        float acc[2][4][4];
#pragma unroll
        for (int mi = 0; mi < 2; mi++)
#pragma unroll
            for (int ni = 0; ni < 4; ni++)
#pragma unroll
                for (int r = 0; r < 4; r++) acc[mi][ni][r] = 0.0f;

#pragma unroll
        for (int ks = 0; ks < 8; ks++) {
            int kw = ks * 8 + 2 * tq;
            uint2 ah2[2][2];
#pragma unroll
            for (int mi = 0; mi < 2; mi++) {
                int r = mBase + mi * 16 + gq;
                ah2[mi][0] = *(const uint2*)(smem + SM_AH + r * AS_STR + kw);
                ah2[mi][1] = *(const uint2*)(smem + SM_AH + (r + 8) * AS_STR + kw);
            }
            uint2 bh[4];
#pragma unroll
            for (int ni = 0; ni < 4; ni++) {
                int c = nBase + ni * 8 + gq;
                bh[ni] = *(const uint2*)(smem + SM_WH + c * AS_STR + kw);
            }
#pragma unroll
            for (int mi = 0; mi < 2; mi++)
#pragma unroll
                for (int ni = 0; ni < 4; ni++)
                    mma_fp16(acc[mi][ni], ah2[mi][0].x, ah2[mi][1].x, ah2[mi][0].y, ah2[mi][1].y,
                             bh[ni].x, bh[ni].y);
        }

        size_t rowBase = (size_t)tile * 64;
#pragma unroll
        for (int mi = 0; mi < 2; mi++) {
            int r0 = mBase + mi * 16 + gq;
#pragma unroll
            for (int ni = 0; ni < 4; ni++) {
                int c0 = nBase + ni * 8 + 2 * tq;
                float2 bb = __ldg((const float2*)(b + c0));
                float v0 = elu_fast(acc[mi][ni][0] + bb.x);
                float v1 = elu_fast(acc[mi][ni][1] + bb.y);
                float v2 = elu_fast(acc[mi][ni][2] + bb.x);
                float v3 = elu_fast(acc[mi][ni][3] + bb.y);
                out16[(rowBase + r0) * 64 + (c0 >> 1)] = pack_h2(v0, v1);
                out16[(rowBase + r0 + 8) * 64 + (c0 >> 1)] = pack_h2(v2, v3);
            }
        }
        __syncthreads();
        tile = next;
    }
}

// ---------------- graph readout (64 nodes/block, sums + counts fused) ---------
__global__ void readout_kernel(const uint32_t* __restrict__ h16,
                               const void* __restrict__ gid) {
    int t = threadIdx.x;
    int base = blockIdx.x * 64;
    int is64 = g_is64;
    const __half* hh = (const __half*)h16;
    int cur = load_idx(gid, base, is64);
    float acc = 0.0f;
    int runlen = 0;
    for (int n = 0; n < 64; n++) {
        int node = base + n;
        int g = load_idx(gid, node, is64);
        if (g != cur) {
            atomicAdd(&g_gsum[cur * HIDDEN + t], acc);
            if (t == 0) atomicAdd(&g_gcnt[cur], (float)runlen);
            acc = 0.0f; runlen = 0; cur = g;
        }
        acc += __half2float(hh[(size_t)node * HIDDEN + t]);
        runlen++;
    }
    atomicAdd(&g_gsum[cur * HIDDEN + t], acc);
    if (t == 0) atomicAdd(&g_gcnt[cur], (float)runlen);
}

__global__ void classifier_kernel(const float* __restrict__ Wc,
                                  const float* __restrict__ bc,
                                  float* __restrict__ out) {
    int t = blockIdx.x * blockDim.x + threadIdx.x;
    if (t >= NUM_GRAPHS * OUTDIM) return;
    int g = t / OUTDIM, o = t % OUTDIM;
    float c = fmaxf(g_gcnt[g], 1.0f);
    float inv = 1.0f / c;
    float acc = bc[o];
#pragma unroll 8
    for (int k = 0; k < HIDDEN; k++)
        acc += g_gsum[g * HIDDEN + k] * inv * Wc[k * OUTDIM + o];
    out[t] = acc;
}

// ---------------- launch -------------------------------------------------------
extern "C" void kernel_launch(void* const* d_in, const int* in_sizes, int n_in,
                              void* d_out, int out_size) {
    const float* features = (const float*)d_in[0];
    const void*  src      = d_in[1];
    const void*  dst      = d_in[2];
    const void*  gids     = d_in[3];
    const float* W1 = (const float*)d_in[4];
    const float* b1 = (const float*)d_in[5];
    const float* W2 = (const float*)d_in[6];
    const float* b2 = (const float*)d_in[7];
    const float* W3 = (const float*)d_in[8];
    const float* b3 = (const float*)d_in[9];
    const float* Wc = (const float*)d_in[10];
    const float* bc = (const float*)d_in[11];
    float* out = (float*)d_out;

    uint32_t* h16; cudaGetSymbolAddress((void**)&h16, g_h16);
    uint32_t* ah;  cudaGetSymbolAddress((void**)&ah, g_ah);
    uint32_t* w16; cudaGetSymbolAddress((void**)&w16, g_w16);
    int* deg;      cudaGetSymbolAddress((void**)&deg, g_deg);

    cudaFuncSetAttribute(gemm_tc_kernel,
                         cudaFuncAttributeMaxDynamicSharedMemorySize, GEMM_SMEM_BYTES);

    cudaMemsetAsync(deg, 0, N_NODES * sizeof(int));
    detect_kernel<<<1, 32>>>((const unsigned int*)src);
    prep_build_kernel<<<(N_NODES * HIDDEN / 4) / 256, 256>>>(features, W1, W2, W3, src, dst);

    const int GATHER_BLOCKS = (N_NODES * 32) / 256;
    const int WSZ = HIDDEN * 64;

    gather_kernel<<<GATHER_BLOCKS, 256>>>(h16, ah);
    gemm_tc_kernel<<<GEMM_GRID, 256, GEMM_SMEM_BYTES>>>(ah, w16, b1, h16);
    gather_kernel<<<GATHER_BLOCKS, 256>>>(h16, ah);
    gemm_tc_kernel<<<GEMM_GRID, 256, GEMM_SMEM_BYTES>>>(ah, w16 + WSZ, b2, h16);
    gather_kernel<<<GATHER_BLOCKS, 256>>>(h16, ah);
    gemm_tc_kernel<<<GEMM_GRID, 256, GEMM_SMEM_BYTES>>>(ah, w16 + 2 * WSZ, b3, h16);

    readout_kernel<<<N_NODES / 64, 128>>>(h16, gids);
    classifier_kernel<<<1, NUM_GRAPHS * OUTDIM>>>(Wc, bc, out);
}

// round 16
// speedup vs baseline: 1.1805x; 1.0228x over previous
#include <cuda_runtime.h>
#include <cuda_fp16.h>
#include <math.h>
#include <stdint.h>

#define N_NODES 65536
#define N_EDGES 524288
#define HIDDEN 128
#define OUTDIM 10
#define NUM_GRAPHS 64
#define SLOT_CAP 64

// ---------------- scratch (device globals; no allocation allowed) ----------
__device__ __align__(16) static uint32_t g_h16[(size_t)N_NODES * 64];
__device__ __align__(16) static uint32_t g_ah[(size_t)N_NODES * 64];
__device__ static int      g_deg[N_NODES];
__device__ static int      g_slots[(size_t)N_NODES * SLOT_CAP];
__device__ static float    g_gsum[NUM_GRAPHS * HIDDEN];
__device__ static float    g_gcnt[NUM_GRAPHS];
__device__ static int      g_is64;
__device__ __align__(16) static uint32_t g_w16[3][HIDDEN * 64];

// ---------------- helpers ----------------------------------------------------
__device__ __forceinline__ int kperm(int w) {
    return (w & ~7) | (((w & 3) << 1) | ((w >> 2) & 1));
}

__device__ __forceinline__ float elu_fast(float v) {
    return v > 0.0f ? v : (__expf(v) - 1.0f);
}

__device__ __forceinline__ uint32_t pack_h2(float a, float b) {
    __half2 h = __floats2half2_rn(a, b);
    return *reinterpret_cast<uint32_t*>(&h);
}

__device__ __forceinline__ uint32_t smem_u32(const void* p) {
    uint32_t a;
    asm("{ .reg .u64 t; cvta.to.shared.u64 t, %1; cvt.u32.u64 %0, t; }"
        : "=r"(a) : "l"(p));
    return a;
}

#define CP_ASYNC16(dst_u32, gptr) \
    asm volatile("cp.async.ca.shared.global [%0], [%1], 16;" \
        :: "r"(dst_u32), "l"(gptr) : "memory")
#define CP_COMMIT() asm volatile("cp.async.commit_group;" ::: "memory")
#define CP_WAIT0()  asm volatile("cp.async.wait_group 0;" ::: "memory")

__device__ __forceinline__ void mma_fp16(float* c, uint32_t a0, uint32_t a1,
                                         uint32_t a2, uint32_t a3,
                                         uint32_t b0, uint32_t b1) {
    asm volatile(
        "mma.sync.aligned.m16n8k16.row.col.f32.f16.f16.f32 "
        "{%0,%1,%2,%3}, {%4,%5,%6,%7}, {%8,%9}, {%0,%1,%2,%3};"
        : "+f"(c[0]), "+f"(c[1]), "+f"(c[2]), "+f"(c[3])
        : "r"(a0), "r"(a1), "r"(a2), "r"(a3), "r"(b0), "r"(b1));
}

// ---------------- index dtype detection (1 warp, parallel) -------------------
__global__ void detect_kernel(const unsigned int* __restrict__ w) {
    int lane = threadIdx.x;
    bool zero = true;
#pragma unroll
    for (int j = 0; j < 4; j++) {
        if (w[1 + 2 * (lane + 32 * j)] != 0u) zero = false;
    }
    unsigned int mask = __ballot_sync(0xffffffffu, zero);
    if (lane == 0) g_is64 = (mask == 0xffffffffu) ? 1 : 0;
}

__device__ __forceinline__ int load_idx(const void* p, int i, int is64) {
    if (is64) return (int)((const long long*)p)[i];
    return ((const int*)p)[i];
}

// ---------------- prep+build: W fp16, features fp16, adjacency, zeroing ------
__global__ void prep_build_kernel(const float* __restrict__ features,
                                  const float* __restrict__ W1,
                                  const float* __restrict__ W2,
                                  const float* __restrict__ W3,
                                  const void* __restrict__ src,
                                  const void* __restrict__ dst) {
    int i = blockIdx.x * blockDim.x + threadIdx.x;
    if (i < NUM_GRAPHS * HIDDEN) g_gsum[i] = 0.0f;
    if (i < NUM_GRAPHS) g_gcnt[i] = 0.0f;
    if (i < 3 * HIDDEN * 64) {
        int layer = i / (HIDDEN * 64);
        int rem = i - layer * (HIDDEN * 64);
        int n = rem >> 6, w = rem & 63;
        const float* W = (layer == 0) ? W1 : (layer == 1) ? W2 : W3;
        float v0 = __ldg(W + (2 * w) * HIDDEN + n);
        float v1 = __ldg(W + (2 * w + 1) * HIDDEN + n);
        g_w16[layer][n * 64 + kperm(w)] = pack_h2(v0, v1);
    }
    if (i < N_EDGES) {
        int is64 = g_is64;
        int d = load_idx(dst, i, is64);
        int s = load_idx(src, i, is64);
        int pos = atomicAdd(&g_deg[d], 1);
        if (pos < SLOT_CAP) g_slots[(size_t)d * SLOT_CAP + pos] = s;
    }
    if (i < (N_NODES * HIDDEN) / 4) {
        float4 f = __ldg((const float4*)features + i);
        uint2 u;
        u.x = pack_h2(f.x, f.y);
        u.y = pack_h2(f.z, f.w);
        *((uint2*)g_h16 + i) = u;
    }
}

// ---------------- gather-sum over fp16 rows -> fp16 A plane (permuted) -------
__global__ void gather_kernel(const uint32_t* __restrict__ h16,
                              uint32_t* __restrict__ ah) {
    int w = (blockIdx.x * blockDim.x + threadIdx.x) >> 5;
    int lane = threadIdx.x & 31;
    if (w >= N_NODES) return;
    int deg = g_deg[w];
    if (deg > SLOT_CAP) deg = SLOT_CAP;
    const int* slots = g_slots + (size_t)w * SLOT_CAP;
    int s0 = (lane < deg) ? slots[lane] : 0;
    int s1 = (32 + lane < deg) ? slots[32 + lane] : 0;
    float4 acc = make_float4(0.f, 0.f, 0.f, 0.f);
    int d0 = (deg < 32) ? deg : 32;
    for (int i = 0; i < d0; i++) {
        int s = __shfl_sync(0xffffffffu, s0, i);
        uint2 u = __ldg((const uint2*)(h16 + (size_t)s * 64) + lane);
        float2 f01 = __half22float2(*reinterpret_cast<__half2*>(&u.x));
        float2 f23 = __half22float2(*reinterpret_cast<__half2*>(&u.y));
        acc.x += f01.x; acc.y += f01.y; acc.z += f23.x; acc.w += f23.y;
    }
    for (int i = 32; i < deg; i++) {
        int s = __shfl_sync(0xffffffffu, s1, i - 32);
        uint2 u = __ldg((const uint2*)(h16 + (size_t)s * 64) + lane);
        float2 f01 = __half22float2(*reinterpret_cast<__half2*>(&u.x));
        float2 f23 = __half22float2(*reinterpret_cast<__half2*>(&u.y));
        acc.x += f01.x; acc.y += f01.y; acc.z += f23.x; acc.w += f23.y;
    }
    size_t rowOff = (size_t)w * 64;
    ah[rowOff + kperm(2 * lane)]     = pack_h2(acc.x, acc.y);
    ah[rowOff + kperm(2 * lane + 1)] = pack_h2(acc.z, acc.w);
}

// ---------------- persistent single-pass fp16 mma GEMM (cp.async A) ----------
// 592 CTAs (4/SM). A staged via cp.async (no prefetch registers).
#define AS_STR 68
#define SM_AH 0
#define SM_WH (64 * AS_STR)
#define GEMM_SMEM_WORDS ((64 + 128) * AS_STR)
#define GEMM_SMEM_BYTES (GEMM_SMEM_WORDS * 4)
#define GEMM_GRID 592
#define NUM_TILES (N_NODES / 64)

__global__ void __launch_bounds__(256, 4)
gemm_tc_kernel(const uint32_t* __restrict__ Ah,
               const uint32_t* __restrict__ Wp,
               const float* __restrict__ b, uint32_t* __restrict__ out16) {
    extern __shared__ __align__(16) uint32_t smem[];
    int tid = threadIdx.x;
    int lane = tid & 31, wid = tid >> 5;
    int gq = lane >> 2, tq = lane & 3;
    int warp_m = wid & 1, warp_n = wid >> 1;
    const int mBase = warp_m * 32;
    const int nBase = warp_n * 32;

    // per-thread A-staging addresses (same for every tile)
    int r_st = tid >> 4, c4_st = tid & 15;          // thread covers 4 rows
    uint32_t a_dst0 = smem_u32(smem) + (SM_AH + r_st * 4 * AS_STR + c4_st * 4) * 4;

    // ---- stage W plane once ----
    {
        const uint4* src = (const uint4*)Wp;
        for (int i = tid; i < 128 * 16; i += 256) {
            int n = i >> 4, c4 = i & 15;
            *(uint4*)(smem + SM_WH + n * AS_STR + c4 * 4) = __ldg(src + i);
        }
    }

    int tile = blockIdx.x;
    if (tile < NUM_TILES) {
        const uint4* src = (const uint4*)(Ah + (size_t)tile * 64 * 64);
#pragma unroll
        for (int j = 0; j < 4; j++)
            CP_ASYNC16(a_dst0 + j * AS_STR * 4, src + (r_st * 4 + j) * 16 + c4_st);
        CP_COMMIT();
    }

    while (tile < NUM_TILES) {
        CP_WAIT0();
        __syncthreads();   // A(tile) visible to all warps (and W on first iter)

        float acc[2][4][4];
#pragma unroll
        for (int mi = 0; mi < 2; mi++)
#pragma unroll
            for (int ni = 0; ni < 4; ni++)
#pragma unroll
                for (int r = 0; r < 4; r++) acc[mi][ni][r] = 0.0f;

#pragma unroll
        for (int ks = 0; ks < 8; ks++) {
            int kw = ks * 8 + 2 * tq;
            uint2 ah2[2][2];
#pragma unroll
            for (int mi = 0; mi < 2; mi++) {
                int r = mBase + mi * 16 + gq;
                ah2[mi][0] = *(const uint2*)(smem + SM_AH + r * AS_STR + kw);
                ah2[mi][1] = *(const uint2*)(smem + SM_AH + (r + 8) * AS_STR + kw);
            }
            uint2 bh[4];
#pragma unroll
            for (int ni = 0; ni < 4; ni++) {
                int c = nBase + ni * 8 + gq;
                bh[ni] = *(const uint2*)(smem + SM_WH + c * AS_STR + kw);
            }
#pragma unroll
            for (int mi = 0; mi < 2; mi++)
#pragma unroll
                for (int ni = 0; ni < 4; ni++)
                    mma_fp16(acc[mi][ni], ah2[mi][0].x, ah2[mi][1].x, ah2[mi][0].y, ah2[mi][1].y,
                             bh[ni].x, bh[ni].y);
        }

        __syncthreads();   // all warps done reading A(tile)

        int next = tile + GEMM_GRID;
        if (next < NUM_TILES) {
            const uint4* src = (const uint4*)(Ah + (size_t)next * 64 * 64);
#pragma unroll
            for (int j = 0; j < 4; j++)
                CP_ASYNC16(a_dst0 + j * AS_STR * 4, src + (r_st * 4 + j) * 16 + c4_st);
            CP_COMMIT();
        }

        // ---- epilogue overlaps the cp.async of the next tile ----
        size_t rowBase = (size_t)tile * 64;
#pragma unroll
        for (int mi = 0; mi < 2; mi++) {
            int r0 = mBase + mi * 16 + gq;
#pragma unroll
            for (int ni = 0; ni < 4; ni++) {
                int c0 = nBase + ni * 8 + 2 * tq;
                float2 bb = __ldg((const float2*)(b + c0));
                float v0 = elu_fast(acc[mi][ni][0] + bb.x);
                float v1 = elu_fast(acc[mi][ni][1] + bb.y);
                float v2 = elu_fast(acc[mi][ni][2] + bb.x);
                float v3 = elu_fast(acc[mi][ni][3] + bb.y);
                out16[(rowBase + r0) * 64 + (c0 >> 1)] = pack_h2(v0, v1);
                out16[(rowBase + r0 + 8) * 64 + (c0 >> 1)] = pack_h2(v2, v3);
            }
        }
        tile = next;
    }
}

// ---------------- graph readout (64 nodes/block, sums + counts fused) ---------
__global__ void readout_kernel(const uint32_t* __restrict__ h16,
                               const void* __restrict__ gid) {
    int t = threadIdx.x;
    int base = blockIdx.x * 64;
    int is64 = g_is64;
    const __half* hh = (const __half*)h16;
    int cur = load_idx(gid, base, is64);
    float acc = 0.0f;
    int runlen = 0;
    for (int n = 0; n < 64; n++) {
        int node = base + n;
        int g = load_idx(gid, node, is64);
        if (g != cur) {
            atomicAdd(&g_gsum[cur * HIDDEN + t], acc);
            if (t == 0) atomicAdd(&g_gcnt[cur], (float)runlen);
            acc = 0.0f; runlen = 0; cur = g;
        }
        acc += __half2float(hh[(size_t)node * HIDDEN + t]);
        runlen++;
    }
    atomicAdd(&g_gsum[cur * HIDDEN + t], acc);
    if (t == 0) atomicAdd(&g_gcnt[cur], (float)runlen);
}

__global__ void classifier_kernel(const float* __restrict__ Wc,
                                  const float* __restrict__ bc,
                                  float* __restrict__ out) {
    int t = blockIdx.x * blockDim.x + threadIdx.x;
    if (t >= NUM_GRAPHS * OUTDIM) return;
    int g = t / OUTDIM, o = t % OUTDIM;
    float c = fmaxf(g_gcnt[g], 1.0f);
    float inv = 1.0f / c;
    float acc = bc[o];
#pragma unroll 8
    for (int k = 0; k < HIDDEN; k++)
        acc += g_gsum[g * HIDDEN + k] * inv * Wc[k * OUTDIM + o];
    out[t] = acc;
}

// ---------------- launch -------------------------------------------------------
extern "C" void kernel_launch(void* const* d_in, const int* in_sizes, int n_in,
                              void* d_out, int out_size) {
    const float* features = (const float*)d_in[0];
    const void*  src      = d_in[1];
    const void*  dst      = d_in[2];
    const void*  gids     = d_in[3];
    const float* W1 = (const float*)d_in[4];
    const float* b1 = (const float*)d_in[5];
    const float* W2 = (const float*)d_in[6];
    const float* b2 = (const float*)d_in[7];
    const float* W3 = (const float*)d_in[8];
    const float* b3 = (const float*)d_in[9];
    const float* Wc = (const float*)d_in[10];
    const float* bc = (const float*)d_in[11];
    float* out = (float*)d_out;

    uint32_t* h16; cudaGetSymbolAddress((void**)&h16, g_h16);
    uint32_t* ah;  cudaGetSymbolAddress((void**)&ah, g_ah);
    uint32_t* w16; cudaGetSymbolAddress((void**)&w16, g_w16);
    int* deg;      cudaGetSymbolAddress((void**)&deg, g_deg);

    cudaFuncSetAttribute(gemm_tc_kernel,
                         cudaFuncAttributeMaxDynamicSharedMemorySize, GEMM_SMEM_BYTES);

    cudaMemsetAsync(deg, 0, N_NODES * sizeof(int));
    detect_kernel<<<1, 32>>>((const unsigned int*)src);
    prep_build_kernel<<<(N_NODES * HIDDEN / 4) / 256, 256>>>(features, W1, W2, W3, src, dst);

    const int GATHER_BLOCKS = (N_NODES * 32) / 256;
    const int WSZ = HIDDEN * 64;

    gather_kernel<<<GATHER_BLOCKS, 256>>>(h16, ah);
    gemm_tc_kernel<<<GEMM_GRID, 256, GEMM_SMEM_BYTES>>>(ah, w16, b1, h16);
    gather_kernel<<<GATHER_BLOCKS, 256>>>(h16, ah);
    gemm_tc_kernel<<<GEMM_GRID, 256, GEMM_SMEM_BYTES>>>(ah, w16 + WSZ, b2, h16);
    gather_kernel<<<GATHER_BLOCKS, 256>>>(h16, ah);
    gemm_tc_kernel<<<GEMM_GRID, 256, GEMM_SMEM_BYTES>>>(ah, w16 + 2 * WSZ, b3, h16);

    readout_kernel<<<N_NODES / 64, 128>>>(h16, gids);
    classifier_kernel<<<1, NUM_GRAPHS * OUTDIM>>>(Wc, bc, out);
}

// round 17
// speedup vs baseline: 1.1956x; 1.0127x over previous
#include <cuda_runtime.h>
#include <cuda_fp16.h>
#include <math.h>
#include <stdint.h>

#define N_NODES 65536
#define N_EDGES 524288
#define HIDDEN 128
#define OUTDIM 10
#define NUM_GRAPHS 64
#define SLOT_CAP 64

// ---------------- scratch (device globals; no allocation allowed) ----------
__device__ __align__(16) static uint32_t g_h16[(size_t)N_NODES * 64];
__device__ __align__(16) static uint32_t g_ah[(size_t)N_NODES * 64];
__device__ static int      g_deg[N_NODES];
__device__ static int      g_slots[(size_t)N_NODES * SLOT_CAP];
__device__ static float    g_gsum[NUM_GRAPHS * HIDDEN];
__device__ static float    g_gcnt[NUM_GRAPHS];
__device__ static int      g_is64;
__device__ __align__(16) static uint32_t g_w16[3][HIDDEN * 64];

// ---------------- helpers ----------------------------------------------------
__device__ __forceinline__ int kperm(int w) {
    return (w & ~7) | (((w & 3) << 1) | ((w >> 2) & 1));
}

__device__ __forceinline__ float elu_fast(float v) {
    return v > 0.0f ? v : (__expf(v) - 1.0f);
}

__device__ __forceinline__ uint32_t pack_h2(float a, float b) {
    __half2 h = __floats2half2_rn(a, b);
    return *reinterpret_cast<uint32_t*>(&h);
}

__device__ __forceinline__ __half2 u2h2(uint32_t u) {
    return *reinterpret_cast<__half2*>(&u);
}

__device__ __forceinline__ uint32_t smem_u32(const void* p) {
    uint32_t a;
    asm("{ .reg .u64 t; cvta.to.shared.u64 t, %1; cvt.u32.u64 %0, t; }"
        : "=r"(a) : "l"(p));
    return a;
}

#define CP_ASYNC16(dst_u32, gptr) \
    asm volatile("cp.async.ca.shared.global [%0], [%1], 16;" \
        :: "r"(dst_u32), "l"(gptr) : "memory")
#define CP_COMMIT() asm volatile("cp.async.commit_group;" ::: "memory")
#define CP_WAIT0()  asm volatile("cp.async.wait_group 0;" ::: "memory")

__device__ __forceinline__ void mma_fp16(float* c, uint32_t a0, uint32_t a1,
                                         uint32_t a2, uint32_t a3,
                                         uint32_t b0, uint32_t b1) {
    asm volatile(
        "mma.sync.aligned.m16n8k16.row.col.f32.f16.f16.f32 "
        "{%0,%1,%2,%3}, {%4,%5,%6,%7}, {%8,%9}, {%0,%1,%2,%3};"
        : "+f"(c[0]), "+f"(c[1]), "+f"(c[2]), "+f"(c[3])
        : "r"(a0), "r"(a1), "r"(a2), "r"(a3), "r"(b0), "r"(b1));
}

// ---------------- index dtype detection (1 warp, parallel) -------------------
__global__ void detect_kernel(const unsigned int* __restrict__ w) {
    int lane = threadIdx.x;
    bool zero = true;
#pragma unroll
    for (int j = 0; j < 4; j++) {
        if (w[1 + 2 * (lane + 32 * j)] != 0u) zero = false;
    }
    unsigned int mask = __ballot_sync(0xffffffffu, zero);
    if (lane == 0) g_is64 = (mask == 0xffffffffu) ? 1 : 0;
}

__device__ __forceinline__ int load_idx(const void* p, int i, int is64) {
    if (is64) return (int)((const long long*)p)[i];
    return ((const int*)p)[i];
}

// ---------------- prep+build: W fp16, features fp16, adjacency, zeroing ------
__global__ void prep_build_kernel(const float* __restrict__ features,
                                  const float* __restrict__ W1,
                                  const float* __restrict__ W2,
                                  const float* __restrict__ W3,
                                  const void* __restrict__ src,
                                  const void* __restrict__ dst) {
    int i = blockIdx.x * blockDim.x + threadIdx.x;
    if (i < NUM_GRAPHS * HIDDEN) g_gsum[i] = 0.0f;
    if (i < NUM_GRAPHS) g_gcnt[i] = 0.0f;
    if (i < 3 * HIDDEN * 64) {
        int layer = i / (HIDDEN * 64);
        int rem = i - layer * (HIDDEN * 64);
        int n = rem >> 6, w = rem & 63;
        const float* W = (layer == 0) ? W1 : (layer == 1) ? W2 : W3;
        float v0 = __ldg(W + (2 * w) * HIDDEN + n);
        float v1 = __ldg(W + (2 * w + 1) * HIDDEN + n);
        g_w16[layer][n * 64 + kperm(w)] = pack_h2(v0, v1);
    }
    if (i < N_EDGES) {
        int is64 = g_is64;
        int d = load_idx(dst, i, is64);
        int s = load_idx(src, i, is64);
        int pos = atomicAdd(&g_deg[d], 1);
        if (pos < SLOT_CAP) g_slots[(size_t)d * SLOT_CAP + pos] = s;
    }
    if (i < (N_NODES * HIDDEN) / 4) {
        float4 f = __ldg((const float4*)features + i);
        uint2 u;
        u.x = pack_h2(f.x, f.y);
        u.y = pack_h2(f.z, f.w);
        *((uint2*)g_h16 + i) = u;
    }
}

// ---------------- gather-sum: half2 dual accumulators, unroll-2 --------------
__global__ void gather_kernel(const uint32_t* __restrict__ h16,
                              uint32_t* __restrict__ ah) {
    int w = (blockIdx.x * blockDim.x + threadIdx.x) >> 5;
    int lane = threadIdx.x & 31;
    if (w >= N_NODES) return;
    int deg = g_deg[w];
    if (deg > SLOT_CAP) deg = SLOT_CAP;
    const int* slots = g_slots + (size_t)w * SLOT_CAP;
    int s0 = (lane < deg) ? slots[lane] : 0;
    int s1 = (32 + lane < deg) ? slots[32 + lane] : 0;

    __half2 zero2 = __float2half2_rn(0.0f);
    __half2 aA = zero2, aB = zero2;   // even-neighbor chains (words 0,1)
    __half2 bA = zero2, bB = zero2;   // odd-neighbor chains

    int d0 = (deg < 32) ? deg : 32;
    int i = 0;
    for (; i + 2 <= d0; i += 2) {
        int sa = __shfl_sync(0xffffffffu, s0, i);
        int sb = __shfl_sync(0xffffffffu, s0, i + 1);
        uint2 ua = __ldg((const uint2*)(h16 + (size_t)sa * 64) + lane);
        uint2 ub = __ldg((const uint2*)(h16 + (size_t)sb * 64) + lane);
        aA = __hadd2(aA, u2h2(ua.x)); aB = __hadd2(aB, u2h2(ua.y));
        bA = __hadd2(bA, u2h2(ub.x)); bB = __hadd2(bB, u2h2(ub.y));
    }
    if (i < d0) {
        int sa = __shfl_sync(0xffffffffu, s0, i);
        uint2 ua = __ldg((const uint2*)(h16 + (size_t)sa * 64) + lane);
        aA = __hadd2(aA, u2h2(ua.x)); aB = __hadd2(aB, u2h2(ua.y));
    }
    for (i = 32; i + 2 <= deg; i += 2) {
        int sa = __shfl_sync(0xffffffffu, s1, i - 32);
        int sb = __shfl_sync(0xffffffffu, s1, i - 31);
        uint2 ua = __ldg((const uint2*)(h16 + (size_t)sa * 64) + lane);
        uint2 ub = __ldg((const uint2*)(h16 + (size_t)sb * 64) + lane);
        aA = __hadd2(aA, u2h2(ua.x)); aB = __hadd2(aB, u2h2(ua.y));
        bA = __hadd2(bA, u2h2(ub.x)); bB = __hadd2(bB, u2h2(ub.y));
    }
    if (i < deg) {
        int sa = __shfl_sync(0xffffffffu, s1, i - 32);
        uint2 ua = __ldg((const uint2*)(h16 + (size_t)sa * 64) + lane);
        aA = __hadd2(aA, u2h2(ua.x)); aB = __hadd2(aB, u2h2(ua.y));
    }

    // merge dual chains in fp32
    float2 fa0 = __half22float2(aA), fb0 = __half22float2(bA);
    float2 fa1 = __half22float2(aB), fb1 = __half22float2(bB);
    float x = fa0.x + fb0.x, y = fa0.y + fb0.y;
    float z = fa1.x + fb1.x, v = fa1.y + fb1.y;

    size_t rowOff = (size_t)w * 64;
    ah[rowOff + kperm(2 * lane)]     = pack_h2(x, y);
    ah[rowOff + kperm(2 * lane + 1)] = pack_h2(z, v);
}

// ---------------- persistent single-pass fp16 mma GEMM (cp.async A) ----------
#define AS_STR 68
#define SM_AH 0
#define SM_WH (64 * AS_STR)
#define GEMM_SMEM_WORDS ((64 + 128) * AS_STR)
#define GEMM_SMEM_BYTES (GEMM_SMEM_WORDS * 4)
#define GEMM_GRID 592
#define NUM_TILES (N_NODES / 64)

__global__ void __launch_bounds__(256, 4)
gemm_tc_kernel(const uint32_t* __restrict__ Ah,
               const uint32_t* __restrict__ Wp,
               const float* __restrict__ b, uint32_t* __restrict__ out16) {
    extern __shared__ __align__(16) uint32_t smem[];
    int tid = threadIdx.x;
    int lane = tid & 31, wid = tid >> 5;
    int gq = lane >> 2, tq = lane & 3;
    int warp_m = wid & 1, warp_n = wid >> 1;
    const int mBase = warp_m * 32;
    const int nBase = warp_n * 32;

    int r_st = tid >> 4, c4_st = tid & 15;
    uint32_t a_dst0 = smem_u32(smem) + (SM_AH + r_st * 4 * AS_STR + c4_st * 4) * 4;

    {
        const uint4* src = (const uint4*)Wp;
        for (int i = tid; i < 128 * 16; i += 256) {
            int n = i >> 4, c4 = i & 15;
            *(uint4*)(smem + SM_WH + n * AS_STR + c4 * 4) = __ldg(src + i);
        }
    }

    int tile = blockIdx.x;
    if (tile < NUM_TILES) {
        const uint4* src = (const uint4*)(Ah + (size_t)tile * 64 * 64);
#pragma unroll
        for (int j = 0; j < 4; j++)
            CP_ASYNC16(a_dst0 + j * AS_STR * 4, src + (r_st * 4 + j) * 16 + c4_st);
        CP_COMMIT();
    }

    while (tile < NUM_TILES) {
        CP_WAIT0();
        __syncthreads();

        float acc[2][4][4];
#pragma unroll
        for (int mi = 0; mi < 2; mi++)
#pragma unroll
            for (int ni = 0; ni < 4; ni++)
#pragma unroll
                for (int r = 0; r < 4; r++) acc[mi][ni][r] = 0.0f;

#pragma unroll
        for (int ks = 0; ks < 8; ks++) {
            int kw = ks * 8 + 2 * tq;
            uint2 ah2[2][2];
#pragma unroll
            for (int mi = 0; mi < 2; mi++) {
                int r = mBase + mi * 16 + gq;
                ah2[mi][0] = *(const uint2*)(smem + SM_AH + r * AS_STR + kw);
                ah2[mi][1] = *(const uint2*)(smem + SM_AH + (r + 8) * AS_STR + kw);
            }
            uint2 bh[4];
#pragma unroll
            for (int ni = 0; ni < 4; ni++) {
                int c = nBase + ni * 8 + gq;
                bh[ni] = *(const uint2*)(smem + SM_WH + c * AS_STR + kw);
            }
#pragma unroll
            for (int mi = 0; mi < 2; mi++)
#pragma unroll
                for (int ni = 0; ni < 4; ni++)
                    mma_fp16(acc[mi][ni], ah2[mi][0].x, ah2[mi][1].x, ah2[mi][0].y, ah2[mi][1].y,
                             bh[ni].x, bh[ni].y);
        }

        __syncthreads();

        int next = tile + GEMM_GRID;
        if (next < NUM_TILES) {
            const uint4* src = (const uint4*)(Ah + (size_t)next * 64 * 64);
#pragma unroll
            for (int j = 0; j < 4; j++)
                CP_ASYNC16(a_dst0 + j * AS_STR * 4, src + (r_st * 4 + j) * 16 + c4_st);
            CP_COMMIT();
        }

        size_t rowBase = (size_t)tile * 64;
#pragma unroll
        for (int mi = 0; mi < 2; mi++) {
            int r0 = mBase + mi * 16 + gq;
#pragma unroll
            for (int ni = 0; ni < 4; ni++) {
                int c0 = nBase + ni * 8 + 2 * tq;
                float2 bb = __ldg((const float2*)(b + c0));
                float v0 = elu_fast(acc[mi][ni][0] + bb.x);
                float v1 = elu_fast(acc[mi][ni][1] + bb.y);
                float v2 = elu_fast(acc[mi][ni][2] + bb.x);
                float v3 = elu_fast(acc[mi][ni][3] + bb.y);
                out16[(rowBase + r0) * 64 + (c0 >> 1)] = pack_h2(v0, v1);
                out16[(rowBase + r0 + 8) * 64 + (c0 >> 1)] = pack_h2(v2, v3);
            }
        }
        tile = next;
    }
}

// ---------------- graph readout (64 nodes/block, sums + counts fused) ---------
__global__ void readout_kernel(const uint32_t* __restrict__ h16,
                               const void* __restrict__ gid) {
    int t = threadIdx.x;
    int base = blockIdx.x * 64;
    int is64 = g_is64;
    const __half* hh = (const __half*)h16;
    int cur = load_idx(gid, base, is64);
    float acc = 0.0f;
    int runlen = 0;
    for (int n = 0; n < 64; n++) {
        int node = base + n;
        int g = load_idx(gid, node, is64);
        if (g != cur) {
            atomicAdd(&g_gsum[cur * HIDDEN + t], acc);
            if (t == 0) atomicAdd(&g_gcnt[cur], (float)runlen);
            acc = 0.0f; runlen = 0; cur = g;
        }
        acc += __half2float(hh[(size_t)node * HIDDEN + t]);
        runlen++;
    }
    atomicAdd(&g_gsum[cur * HIDDEN + t], acc);
    if (t == 0) atomicAdd(&g_gcnt[cur], (float)runlen);
}

__global__ void classifier_kernel(const float* __restrict__ Wc,
                                  const float* __restrict__ bc,
                                  float* __restrict__ out) {
    int t = blockIdx.x * blockDim.x + threadIdx.x;
    if (t >= NUM_GRAPHS * OUTDIM) return;
    int g = t / OUTDIM, o = t % OUTDIM;
    float c = fmaxf(g_gcnt[g], 1.0f);
    float inv = 1.0f / c;
    float acc = bc[o];
#pragma unroll 8
    for (int k = 0; k < HIDDEN; k++)
        acc += g_gsum[g * HIDDEN + k] * inv * Wc[k * OUTDIM + o];
    out[t] = acc;
}

// ---------------- launch -------------------------------------------------------
extern "C" void kernel_launch(void* const* d_in, const int* in_sizes, int n_in,
                              void* d_out, int out_size) {
    const float* features = (const float*)d_in[0];
    const void*  src      = d_in[1];
    const void*  dst      = d_in[2];
    const void*  gids     = d_in[3];
    const float* W1 = (const float*)d_in[4];
    const float* b1 = (const float*)d_in[5];
    const float* W2 = (const float*)d_in[6];
    const float* b2 = (const float*)d_in[7];
    const float* W3 = (const float*)d_in[8];
    const float* b3 = (const float*)d_in[9];
    const float* Wc = (const float*)d_in[10];
    const float* bc = (const float*)d_in[11];
    float* out = (float*)d_out;

    uint32_t* h16; cudaGetSymbolAddress((void**)&h16, g_h16);
    uint32_t* ah;  cudaGetSymbolAddress((void**)&ah, g_ah);
    uint32_t* w16; cudaGetSymbolAddress((void**)&w16, g_w16);
    int* deg;      cudaGetSymbolAddress((void**)&deg, g_deg);

    cudaFuncSetAttribute(gemm_tc_kernel,
                         cudaFuncAttributeMaxDynamicSharedMemorySize, GEMM_SMEM_BYTES);

    cudaMemsetAsync(deg, 0, N_NODES * sizeof(int));
    detect_kernel<<<1, 32>>>((const unsigned int*)src);
    prep_build_kernel<<<(N_NODES * HIDDEN / 4) / 256, 256>>>(features, W1, W2, W3, src, dst);

    const int GATHER_BLOCKS = (N_NODES * 32) / 256;
    const int WSZ = HIDDEN * 64;

    gather_kernel<<<GATHER_BLOCKS, 256>>>(h16, ah);
    gemm_tc_kernel<<<GEMM_GRID, 256, GEMM_SMEM_BYTES>>>(ah, w16, b1, h16);
    gather_kernel<<<GATHER_BLOCKS, 256>>>(h16, ah);
    gemm_tc_kernel<<<GEMM_GRID, 256, GEMM_SMEM_BYTES>>>(ah, w16 + WSZ, b2, h16);
    gather_kernel<<<GATHER_BLOCKS, 256>>>(h16, ah);
    gemm_tc_kernel<<<GEMM_GRID, 256, GEMM_SMEM_BYTES>>>(ah, w16 + 2 * WSZ, b3, h16);

    readout_kernel<<<N_NODES / 64, 128>>>(h16, gids);
    classifier_kernel<<<1, NUM_GRAPHS * OUTDIM>>>(Wc, bc, out);
}